// round 9
// baseline (speedup 1.0000x reference)
#include <cuda_runtime.h>
#include <cuda_bf16.h>
#include <cstdint>

#define NUM_TAGS 48
#define SEQ_LEN  512
#define BATCH    1024
#define CHUNK    8
#define NCHUNK   (SEQ_LEN / CHUNK)   // 64

__device__ float    g_nll[BATCH];
__device__ unsigned g_count = 0;

// ---- packed f32x2 helpers (Blackwell FFMA2/FMUL2/FADD2 path, PTX-only) -------
__device__ __forceinline__ void fma2(uint64_t& d, uint64_t a, uint64_t b) {
    asm("fma.rn.f32x2 %0, %1, %2, %0;" : "+l"(d) : "l"(a), "l"(b));
}
__device__ __forceinline__ uint64_t add2(uint64_t a, uint64_t b) {
    uint64_t d;
    asm("add.rn.f32x2 %0, %1, %2;" : "=l"(d) : "l"(a), "l"(b));
    return d;
}
__device__ __forceinline__ uint64_t mul2(uint64_t a, uint64_t b) {
    uint64_t d;
    asm("mul.rn.f32x2 %0, %1, %2;" : "=l"(d) : "l"(a), "l"(b));
    return d;
}
__device__ __forceinline__ uint64_t pack2(float lo, float hi) {
    uint64_t d;
    asm("mov.b64 %0, {%1, %2};" : "=l"(d) : "f"(lo), "f"(hi));
    return d;
}
__device__ __forceinline__ float lo2(uint64_t v) { return __uint_as_float((uint32_t)v); }
__device__ __forceinline__ float hi2(uint64_t v) { return __uint_as_float((uint32_t)(v >> 32)); }

__device__ __forceinline__ void cp16(uint32_t saddr, const void* g) {
    asm volatile("cp.async.cg.shared.global [%0], [%1], 16;" :: "r"(saddr), "l"(g));
}

// One warp (one CTA) per batch element. 12x4 layout: active lanes are
// (h = lane>>4, q = lane&15 with q<12); lane owns outputs {4q..4q+3}; K is
// split in halves of 24 by h and combined with one 64-bit butterfly (XOR 16).
// Alignment: alpha store = STS.128, emission read = LDS.128.
__global__ __launch_bounds__(32)
void crf_fused_kernel(const float* __restrict__ emissions,
                      const float* __restrict__ transitions,
                      const int*   __restrict__ tags,
                      const int*   __restrict__ mask,
                      float*       __restrict__ out)
{
    const int lane = threadIdx.x;
    const int b    = blockIdx.x;
    const int h    = lane >> 4;           // K half: [24h, 24h+24)
    const int q    = lane & 15;
    const bool act = (q < 12);            // 24 active lanes own 48 outputs
    const int jc0  = 4 * (act ? q : 11);  // owned column base (clamped for idle)
    const int i0   = 24 * h;

    __shared__ __align__(16) float swbuf[2][NUM_TAGS];        // alpha ping-pong
    __shared__ __align__(16) float sem[2][CHUNK * NUM_TAGS];  // emission chunks
    __shared__ int stags[SEQ_LEN];
    __shared__ int smask[SEQ_LEN];

    const float* em_b   = emissions + (size_t)b * SEQ_LEN * NUM_TAGS;
    const int*   tags_b = tags + b * SEQ_LEN;
    const int*   mask_b = mask + b * SEQ_LEN;

    // --- stage emission chunk 0 ----------------------------------------------
    {
        uint32_t dst = (uint32_t)__cvta_generic_to_shared(&sem[0][0]);
        #pragma unroll
        for (int r = 0; r < 3; r++)
            cp16(dst + lane * 16 + r * 512, em_b + lane * 4 + r * 128);
        asm volatile("cp.async.commit_group;");
    }

    // --- tags / mask to shared --------------------------------------------------
    #pragma unroll
    for (int r = 0; r < 4; r++) {
        ((int4*)stags)[lane + 32 * r] = ((const int4*)tags_b)[lane + 32 * r];
        ((int4*)smask)[lane + 32 * r] = ((const int4*)mask_b)[lane + 32 * r];
    }

    // --- E = exp(T): 4 owned columns x 24 input rows (this lane's K half) --------
    // Ec[cc*12+k] = (exp T[i0+2k][jc0+cc], exp T[i0+2k+1][jc0+cc])
    uint64_t Ec[48];
    #pragma unroll
    for (int cc = 0; cc < 4; cc++)
        #pragma unroll
        for (int k = 0; k < 12; k++)
            Ec[cc * 12 + k] = pack2(__expf(transitions[(i0 + 2 * k    ) * NUM_TAGS + jc0 + cc]),
                                    __expf(transitions[(i0 + 2 * k + 1) * NUM_TAGS + jc0 + cc]));

    // --- init alphas (linear): only tag 0 live ------------------------------------
    uint64_t w01 = pack2((q == 0) ? 1.0f : 0.0f, 0.0f);
    uint64_t w23 = 0;
    if (act) *(ulonglong2*)(&swbuf[0][jc0]) = make_ulonglong2(w01, w23);
    __syncwarp();

    // --- gold-path score (overlaps staged chunk-0 latency) -------------------------
    float sc = 0.0f;
    #pragma unroll 4
    for (int t = 1 + lane; t < SEQ_LEN; t += 32) {
        int tc = stags[t], tp = stags[t - 1];
        if (smask[t])
            sc += em_b[(size_t)t * NUM_TAGS + tc] + transitions[tp * NUM_TAGS + tc];
    }
    #pragma unroll
    for (int off = 16; off; off >>= 1)
        sc += __shfl_xor_sync(0xffffffffu, sc, off);

    // --- forward recursion: 64 chunks x 8 steps -------------------------------------
    float C = 0.0f;
    float carry_inv = 1.0f;   // pending renorm scale (exact once logged)

    for (int c = 0; c < NCHUNK; c++) {
        if (c + 1 < NCHUNK) {
            uint32_t dst = (uint32_t)__cvta_generic_to_shared(&sem[(c + 1) & 1][0]);
            const float* src = em_b + (size_t)(c + 1) * CHUNK * NUM_TAGS;
            #pragma unroll
            for (int r = 0; r < 3; r++)
                cp16(dst + lane * 16 + r * 512, src + lane * 4 + r * 128);
        }
        asm volatile("cp.async.commit_group;");
        asm volatile("cp.async.wait_group 1;");
        __syncwarp();

        const float* eb = sem[c & 1];

        // hoist emission exps, packed: one LDS.128 per step
        uint64_t eE01[CHUNK], eE23[CHUNK];
        #pragma unroll
        for (int u = 0; u < CHUNK; u++) {
            float4 ev = *(const float4*)&eb[u * NUM_TAGS + jc0];
            eE01[u] = pack2(__expf(ev.x), __expf(ev.y));
            eE23[u] = pack2(__expf(ev.z), __expf(ev.w));
        }

        const int4 ma  = ((const int4*)(smask + c * CHUNK))[0];
        const int4 mbq = ((const int4*)(smask + c * CHUNK))[1];
        const int mall = ma.x & ma.y & ma.z & ma.w & mbq.x & mbq.y & mbq.z & mbq.w;

        if (mall) {
            // fast path: fold pending scale into step 0's emission factor
            {
                uint64_t ci2 = pack2(carry_inv, carry_inv);
                eE01[0] = mul2(eE01[0], ci2);
                eE23[0] = mul2(eE23[0], ci2);
            }
            #pragma unroll
            for (int u = 0; u < CHUNK; u++) {
                const ulonglong2* wv = (const ulonglong2*)(&swbuf[u & 1][i0]);
                uint64_t a0[4] = {0,0,0,0}, a1[4] = {0,0,0,0};
                #pragma unroll
                for (int r = 0; r < 6; r++) {
                    ulonglong2 W = wv[r];
                    #pragma unroll
                    for (int cc = 0; cc < 4; cc++) {
                        fma2(a0[cc], W.x, Ec[cc * 12 + 2 * r]);
                        fma2(a1[cc], W.y, Ec[cc * 12 + 2 * r + 1]);
                    }
                }
                float d[4];
                #pragma unroll
                for (int cc = 0; cc < 4; cc++) {
                    uint64_t s = add2(a0[cc], a1[cc]);
                    d[cc] = lo2(s) + hi2(s);               // own half-dot
                }
                uint64_t p01 = pack2(d[0], d[1]);
                uint64_t p23 = pack2(d[2], d[3]);
                p01 = add2(p01, __shfl_xor_sync(0xffffffffu, p01, 16));
                p23 = add2(p23, __shfl_xor_sync(0xffffffffu, p23, 16));
                w01 = mul2(p01, eE01[u]);
                w23 = mul2(p23, eE23[u]);
                if (act)
                    *(ulonglong2*)(&swbuf[(u & 1) ^ 1][jc0]) = make_ulonglong2(w01, w23);
                asm volatile("" ::: "memory");
            }
        } else {
            // slow path (general mask): apply pending scale first, then selects
            {
                uint64_t ci2 = pack2(carry_inv, carry_inv);
                w01 = mul2(w01, ci2);
                w23 = mul2(w23, ci2);
                carry_inv = 1.0f;
                if (act)
                    *(ulonglong2*)(&swbuf[0][jc0]) = make_ulonglong2(w01, w23);
                __syncwarp();
            }
            #pragma unroll
            for (int u = 0; u < CHUNK; u++) {
                const ulonglong2* wv = (const ulonglong2*)(&swbuf[u & 1][i0]);
                uint64_t a0[4] = {0,0,0,0}, a1[4] = {0,0,0,0};
                #pragma unroll
                for (int r = 0; r < 6; r++) {
                    ulonglong2 W = wv[r];
                    #pragma unroll
                    for (int cc = 0; cc < 4; cc++) {
                        fma2(a0[cc], W.x, Ec[cc * 12 + 2 * r]);
                        fma2(a1[cc], W.y, Ec[cc * 12 + 2 * r + 1]);
                    }
                }
                float d[4];
                #pragma unroll
                for (int cc = 0; cc < 4; cc++) {
                    uint64_t s = add2(a0[cc], a1[cc]);
                    d[cc] = lo2(s) + hi2(s);
                }
                uint64_t p01 = pack2(d[0], d[1]);
                uint64_t p23 = pack2(d[2], d[3]);
                p01 = add2(p01, __shfl_xor_sync(0xffffffffu, p01, 16));
                p23 = add2(p23, __shfl_xor_sync(0xffffffffu, p23, 16));
                uint64_t n01 = mul2(p01, eE01[u]);
                uint64_t n23 = mul2(p23, eE23[u]);
                int m = smask[c * CHUNK + u];
                w01 = m ? n01 : w01;
                w23 = m ? n23 : w23;
                if (act)
                    *(ulonglong2*)(&swbuf[(u & 1) ^ 1][jc0]) = make_ulonglong2(w01, w23);
                __syncwarp();
            }
        }

        // lazy renorm: scale by alpha[0] (>0 always); exact once logged
        float s = __shfl_sync(0xffffffffu, lo2(w01), 0);
        C += __logf(s);
        carry_inv = __fdividef(1.0f, s);
    }

    // --- final partition: logZ = C + log( (sum w) * carry_inv ) ---------------------
    float v = 0.0f;
    if (act && h == 0) {
        v = lo2(w01) + hi2(w01) + lo2(w23) + hi2(w23);
    }
    #pragma unroll
    for (int off = 16; off; off >>= 1)
        v += __shfl_xor_sync(0xffffffffu, v, off);
    if (lane == 0) {
        float logZ  = C + __logf(v * carry_inv);
        float score = sc + em_b[stags[0]];           // emit[0] always counted
        g_nll[b] = logZ - score;
    }

    // --- fused mean-reduce: last CTA does the deterministic sum ---------------------
    unsigned done = 0;
    if (lane == 0) {
        __threadfence();
        done = atomicAdd(&g_count, 1u);
    }
    done = __shfl_sync(0xffffffffu, done, 0);
    if (done == BATCH - 1) {
        __threadfence();
        float r = 0.0f;
        #pragma unroll
        for (int i = lane; i < BATCH; i += 32)
            r += __ldcg(&g_nll[i]);
        #pragma unroll
        for (int off = 16; off; off >>= 1)
            r += __shfl_xor_sync(0xffffffffu, r, off);
        if (lane == 0) {
            out[0] = r * (1.0f / (float)BATCH);
            g_count = 0;   // reset for next graph replay
        }
    }
}

extern "C" void kernel_launch(void* const* d_in, const int* in_sizes, int n_in,
                              void* d_out, int out_size)
{
    const float* emissions   = (const float*)d_in[0];
    const float* transitions = (const float*)d_in[1];
    const int*   tags        = (const int*)d_in[2];
    const int*   mask        = (const int*)d_in[3];
    float*       out         = (float*)d_out;

    crf_fused_kernel<<<BATCH, 32>>>(emissions, transitions, tags, mask, out);
}

// round 10
// speedup vs baseline: 1.1886x; 1.1886x over previous
#include <cuda_runtime.h>
#include <cuda_bf16.h>
#include <cstdint>

#define NUM_TAGS 48
#define SEQ_LEN  512
#define BATCH    1024
#define CHUNK    8
#define NCHUNK   (SEQ_LEN / CHUNK)   // 64

__device__ float    g_nll[BATCH];
__device__ unsigned g_count = 0;

__device__ __forceinline__ void cp16(uint32_t saddr, const void* g) {
    asm volatile("cp.async.cg.shared.global [%0], [%1], 16;" :: "r"(saddr), "l"(g));
}

// One warp (one CTA) per batch element. Scalar-FFMA inner loop (no f32x2 PTX),
// triple-buffered cp.async emission staging, lazy per-chunk renorm, step loop
// free of WARPSYNC (full-mask shfl anchors convergence; all lanes store
// bit-identical duplicates).
__global__ __launch_bounds__(32)
void crf_fused_kernel(const float* __restrict__ emissions,
                      const float* __restrict__ transitions,
                      const int*   __restrict__ tags,
                      const int*   __restrict__ mask,
                      float*       __restrict__ out)
{
    const int lane = threadIdx.x;
    const int b    = blockIdx.x;
    const int h    = lane >> 4;     // K half: rows [24h, 24h+24)
    const int q    = lane & 15;     // owned output triple {3q,3q+1,3q+2}
    const int j0   = 3 * q;
    const int i0   = 24 * h;

    __shared__ __align__(16) float swbuf[2][NUM_TAGS];        // alpha ping-pong
    __shared__ __align__(16) float sem[3][CHUNK * NUM_TAGS];  // emission chunks (3-deep)
    __shared__ int stags[SEQ_LEN];
    __shared__ int smask[SEQ_LEN];

    const float* em_b   = emissions + (size_t)b * SEQ_LEN * NUM_TAGS;
    const int*   tags_b = tags + b * SEQ_LEN;
    const int*   mask_b = mask + b * SEQ_LEN;

    // --- stage emission chunks 0 and 1 (two pending groups) --------------------
    #pragma unroll
    for (int pc = 0; pc < 2; pc++) {
        uint32_t dst = (uint32_t)__cvta_generic_to_shared(&sem[pc][0]);
        const float* src = em_b + (size_t)pc * CHUNK * NUM_TAGS;
        #pragma unroll
        for (int r = 0; r < 3; r++)
            cp16(dst + lane * 16 + r * 512, src + lane * 4 + r * 128);
        asm volatile("cp.async.commit_group;");
    }

    // --- tags / mask to shared ---------------------------------------------------
    #pragma unroll
    for (int r = 0; r < 4; r++) {
        ((int4*)stags)[lane + 32 * r] = ((const int4*)tags_b)[lane + 32 * r];
        ((int4*)smask)[lane + 32 * r] = ((const int4*)mask_b)[lane + 32 * r];
    }

    // --- E = exp(T): scalar registers, 3 owned columns x 24 input rows -----------
    float E0[24], E1[24], E2[24];
    #pragma unroll
    for (int k = 0; k < 24; k++) {
        E0[k] = __expf(transitions[(i0 + k) * NUM_TAGS + j0]);
        E1[k] = __expf(transitions[(i0 + k) * NUM_TAGS + j0 + 1]);
        E2[k] = __expf(transitions[(i0 + k) * NUM_TAGS + j0 + 2]);
    }

    // --- init alphas (linear): only tag 0 live ------------------------------------
    float w0 = (q == 0) ? 1.0f : 0.0f;
    float w1 = 0.0f, w2 = 0.0f;
    swbuf[0][j0]     = w0;    // all lanes store (q / q+16 duplicates identical)
    swbuf[0][j0 + 1] = w1;
    swbuf[0][j0 + 2] = w2;
    __syncwarp();

    // --- gold-path score (overlaps staged-chunk latency) --------------------------
    float sc = 0.0f;
    #pragma unroll 4
    for (int t = 1 + lane; t < SEQ_LEN; t += 32) {
        int tc = stags[t], tp = stags[t - 1];
        if (smask[t])
            sc += em_b[(size_t)t * NUM_TAGS + tc] + transitions[tp * NUM_TAGS + tc];
    }
    #pragma unroll
    for (int off = 16; off; off >>= 1)
        sc += __shfl_xor_sync(0xffffffffu, sc, off);

    // --- forward recursion: 64 chunks x 8 steps ------------------------------------
    float C = 0.0f;
    float carry_inv = 1.0f;   // pending renorm scale (exact once logged)

    for (int c = 0; c < NCHUNK; c++) {
        // prefetch chunk c+2 (keep 2 groups in flight)
        if (c + 2 < NCHUNK) {
            uint32_t dst = (uint32_t)__cvta_generic_to_shared(&sem[(c + 2) % 3][0]);
            const float* src = em_b + (size_t)(c + 2) * CHUNK * NUM_TAGS;
            #pragma unroll
            for (int r = 0; r < 3; r++)
                cp16(dst + lane * 16 + r * 512, src + lane * 4 + r * 128);
        }
        asm volatile("cp.async.commit_group;");
        asm volatile("cp.async.wait_group 2;");   // chunk c resident
        __syncwarp();

        const float* eb = sem[c % 3];

        // hoist emission exps for this chunk (off the recurrence chain)
        float eE[CHUNK][3];
        #pragma unroll
        for (int u = 0; u < CHUNK; u++) {
            eE[u][0] = __expf(eb[u * NUM_TAGS + j0]);
            eE[u][1] = __expf(eb[u * NUM_TAGS + j0 + 1]);
            eE[u][2] = __expf(eb[u * NUM_TAGS + j0 + 2]);
        }

        const int4 ma  = ((const int4*)(smask + c * CHUNK))[0];
        const int4 mbq = ((const int4*)(smask + c * CHUNK))[1];
        const int mall = ma.x & ma.y & ma.z & ma.w & mbq.x & mbq.y & mbq.z & mbq.w;

        if (mall) {
            // fast path: fold pending scale into step 0's emission factor
            eE[0][0] *= carry_inv; eE[0][1] *= carry_inv; eE[0][2] *= carry_inv;

            #pragma unroll
            for (int u = 0; u < CHUNK; u++) {
                const float* wv = &swbuf[u & 1][i0];
                float W[24];
                #pragma unroll
                for (int r = 0; r < 6; r++)
                    *(float4*)&W[4 * r] = *(const float4*)&wv[4 * r];

                float a0 = 0.f, b0 = 0.f, a1 = 0.f, b1 = 0.f, a2 = 0.f, b2 = 0.f;
                #pragma unroll
                for (int k = 0; k < 24; k += 2) {
                    a0 += W[k] * E0[k];  b0 += W[k + 1] * E0[k + 1];
                    a1 += W[k] * E1[k];  b1 += W[k + 1] * E1[k + 1];
                    a2 += W[k] * E2[k];  b2 += W[k + 1] * E2[k + 1];
                }
                float d0 = a0 + b0, d1 = a1 + b1, d2 = a2 + b2;
                d0 += __shfl_xor_sync(0xffffffffu, d0, 16);   // combine K halves
                d1 += __shfl_xor_sync(0xffffffffu, d1, 16);
                d2 += __shfl_xor_sync(0xffffffffu, d2, 16);
                w0 = d0 * eE[u][0];
                w1 = d1 * eE[u][1];
                w2 = d2 * eE[u][2];
                float* wd = swbuf[(u & 1) ^ 1];
                wd[j0]     = w0;    // all lanes store; pair-identical values
                wd[j0 + 1] = w1;
                wd[j0 + 2] = w2;
                asm volatile("" ::: "memory");
            }
        } else {
            // slow path (general mask): apply pending scale, then select-based steps
            w0 *= carry_inv; w1 *= carry_inv; w2 *= carry_inv;
            carry_inv = 1.0f;
            swbuf[0][j0] = w0; swbuf[0][j0 + 1] = w1; swbuf[0][j0 + 2] = w2;
            __syncwarp();

            #pragma unroll
            for (int u = 0; u < CHUNK; u++) {
                const float* wv = &swbuf[u & 1][i0];
                float W[24];
                #pragma unroll
                for (int r = 0; r < 6; r++)
                    *(float4*)&W[4 * r] = *(const float4*)&wv[4 * r];

                float a0 = 0.f, b0 = 0.f, a1 = 0.f, b1 = 0.f, a2 = 0.f, b2 = 0.f;
                #pragma unroll
                for (int k = 0; k < 24; k += 2) {
                    a0 += W[k] * E0[k];  b0 += W[k + 1] * E0[k + 1];
                    a1 += W[k] * E1[k];  b1 += W[k + 1] * E1[k + 1];
                    a2 += W[k] * E2[k];  b2 += W[k + 1] * E2[k + 1];
                }
                float d0 = a0 + b0, d1 = a1 + b1, d2 = a2 + b2;
                d0 += __shfl_xor_sync(0xffffffffu, d0, 16);
                d1 += __shfl_xor_sync(0xffffffffu, d1, 16);
                d2 += __shfl_xor_sync(0xffffffffu, d2, 16);
                float n0 = d0 * eE[u][0];
                float n1 = d1 * eE[u][1];
                float n2 = d2 * eE[u][2];
                int m = smask[c * CHUNK + u];
                w0 = m ? n0 : w0;
                w1 = m ? n1 : w1;
                w2 = m ? n2 : w2;
                float* wd = swbuf[(u & 1) ^ 1];
                wd[j0] = w0; wd[j0 + 1] = w1; wd[j0 + 2] = w2;
                __syncwarp();
            }
        }

        // lazy renorm: scale by alpha[0] (>0 always); exact once logged
        float s = __shfl_sync(0xffffffffu, w0, 0);
        C += __logf(s);
        carry_inv = __fdividef(1.0f, s);
    }

    // --- final partition: logZ = C + log( (sum w) * carry_inv ) ---------------------
    float v = (h == 0) ? (w0 + w1 + w2) : 0.0f;
    #pragma unroll
    for (int off = 16; off; off >>= 1)
        v += __shfl_xor_sync(0xffffffffu, v, off);
    if (lane == 0) {
        float logZ  = C + __logf(v * carry_inv);
        float score = sc + em_b[stags[0]];           // emit[0] always counted
        g_nll[b] = logZ - score;
    }

    // --- fused mean-reduce: last CTA does the deterministic sum ---------------------
    unsigned done = 0;
    if (lane == 0) {
        __threadfence();
        done = atomicAdd(&g_count, 1u);
    }
    done = __shfl_sync(0xffffffffu, done, 0);
    if (done == BATCH - 1) {
        __threadfence();
        float r = 0.0f;
        #pragma unroll
        for (int i = lane; i < BATCH; i += 32)
            r += __ldcg(&g_nll[i]);
        #pragma unroll
        for (int off = 16; off; off >>= 1)
            r += __shfl_xor_sync(0xffffffffu, r, off);
        if (lane == 0) {
            out[0] = r * (1.0f / (float)BATCH);
            g_count = 0;   // reset for next graph replay
        }
    }
}

extern "C" void kernel_launch(void* const* d_in, const int* in_sizes, int n_in,
                              void* d_out, int out_size)
{
    const float* emissions   = (const float*)d_in[0];
    const float* transitions = (const float*)d_in[1];
    const int*   tags        = (const int*)d_in[2];
    const int*   mask        = (const int*)d_in[3];
    float*       out         = (float*)d_out;

    crf_fused_kernel<<<BATCH, 32>>>(emissions, transitions, tags, mask, out);
}